// round 12
// baseline (speedup 1.0000x reference)
#include <cuda_runtime.h>
#include <cuda_bf16.h>
#include <math.h>
#include <stdint.h>

#define LN_EPS 1e-5f

// Problem constants
constexpr int CB = 4, CS = 2048, CD = 2048, CF = 8192;
constexpr int CM = CB * CS;
constexpr int MCHUNK = 2048;
constexpr int NCHUNKS = CM / MCHUNK;

// GEMM tiling
constexpr int BM = 128, BN = 64, BK = 32;
constexpr int THREADS = 256;     // 8 warps: 4 (M) x 2 (N)
constexpr int RW = 16;           // smem row pitch in words (swizzled, no pad)

// Smem layout (words): per stage, 4 A planes then 4 B planes.
constexpr int A_PL = BM * RW;                // 2048 words
constexpr int B_PL = BN * RW;                // 1024 words
constexpr int B_OFF = 4 * A_PL;              // 8192
constexpr int STAGE_W = 4 * A_PL + 4 * B_PL; // 12288 words
constexpr int SMEM_BYTES = 2 * STAGE_W * 4;  // 98304 B -> 2 CTAs/SM

// ---- device-global scratch: packed bf16x2 hi/lo planes (word = k,k+1) ----
constexpr size_t XW = (size_t)CM * CD / 2;
constexpr size_t WW = (size_t)CF * CD / 2;
constexpr size_t UW = (size_t)MCHUNK * CF / 2;
__device__ __align__(16) uint32_t g_cX_hr[XW], g_cX_lr[XW], g_cX_hi[XW], g_cX_li[XW];
__device__ __align__(16) uint32_t g_cWu_hr[WW], g_cWu_lr[WW], g_cWu_hi[WW], g_cWu_li[WW];
__device__ __align__(16) uint32_t g_cWd_hr[WW], g_cWd_lr[WW], g_cWd_hi[WW], g_cWd_li[WW];
__device__ __align__(16) uint32_t g_cUp_hr[UW], g_cUp_lr[UW], g_cUp_hi[UW], g_cUp_li[UW];
__device__ __align__(16) float g_dn_re[(size_t)MCHUNK * CD];
__device__ __align__(16) float g_dn_im[(size_t)MCHUNK * CD];

// Split two fp32 into packed bf16 hi / lo words
__device__ __forceinline__ void split2(float x, float y, uint32_t& hi, uint32_t& lo) {
    __nv_bfloat16 xh = __float2bfloat16_rn(x);
    __nv_bfloat16 yh = __float2bfloat16_rn(y);
    float xr = x - __bfloat162float(xh);
    float yr = y - __bfloat162float(yh);
    __nv_bfloat16 xl = __float2bfloat16_rn(xr);
    __nv_bfloat16 yl = __float2bfloat16_rn(yr);
    hi = (uint32_t)__bfloat16_as_ushort(xh) | ((uint32_t)__bfloat16_as_ushort(yh) << 16);
    lo = (uint32_t)__bfloat16_as_ushort(xl) | ((uint32_t)__bfloat16_as_ushort(yl) << 16);
}

__device__ __forceinline__ void mma16816(float* c, const uint32_t* a, const uint32_t* b) {
    asm volatile(
        "mma.sync.aligned.m16n8k16.row.col.f32.bf16.bf16.f32 "
        "{%0,%1,%2,%3}, {%4,%5,%6,%7}, {%8,%9}, {%0,%1,%2,%3};\n"
        : "+f"(c[0]), "+f"(c[1]), "+f"(c[2]), "+f"(c[3])
        : "r"(a[0]), "r"(a[1]), "r"(a[2]), "r"(a[3]), "r"(b[0]), "r"(b[1]));
}

__device__ __forceinline__ void cpasync16(uint32_t smem_bytes_addr, const void* g) {
    asm volatile("cp.async.cg.shared.global [%0], [%1], 16;\n"
                 :: "r"(smem_bytes_addr), "l"(g));
}
#define CP_COMMIT() asm volatile("cp.async.commit_group;\n")
template <int N>
__device__ __forceinline__ void cp_wait() {
    asm volatile("cp.async.wait_group %0;\n" :: "n"(N));
}

// Swizzled word index within a plane: row pitch 16 words, 16B-chunk XOR.
__device__ __forceinline__ int swz(int row, int kb) {
    return row * RW + ((((kb >> 2) ^ ((row >> 1) & 3)) << 2) | (kb & 3));
}

// Pre-conversion: fp32 planar -> packed bf16x2 hi/lo planes.
__global__ void __launch_bounds__(256)
conv_kernel(const float* __restrict__ re, const float* __restrict__ im,
            uint32_t* __restrict__ hr, uint32_t* __restrict__ lr,
            uint32_t* __restrict__ hi_, uint32_t* __restrict__ li,
            size_t nwords, size_t lim) {
    size_t i = (size_t)blockIdx.x * 256 + threadIdx.x;
    if (i >= nwords) return;
    size_t e = 2 * i;
    float r0 = 0.f, r1 = 0.f, q0 = 0.f, q1 = 0.f;
    if (e + 2 <= lim) {
        float2 v = *reinterpret_cast<const float2*>(re + e);
        float2 w = *reinterpret_cast<const float2*>(im + e);
        r0 = v.x; r1 = v.y; q0 = w.x; q1 = w.y;
    }
    split2(r0, r1, hr[i], lr[i]);
    split2(q0, q1, hi_[i], li[i]);
}

// Complex NT GEMM, compile-time K/N, single-barrier double-buffered mainloop.
// PHASE 0: A = g_cX (rows m_base+..), B = g_cWu, epi = bias+modrelu -> g_cUp
// PHASE 1: A = g_cUp (chunk-local), B = g_cWd, epi = plain -> g_dn
template <int PHASE, int KK, int NN>
__global__ void __launch_bounds__(THREADS, 2)
cgemm_nt(const float* __restrict__ bias_re, const float* __restrict__ bias_im,
         const float* __restrict__ mrb,
         int m_base, size_t bias_lim) {
    extern __shared__ uint32_t s[];
    const uint32_t smem_b = (uint32_t)__cvta_generic_to_shared(s);

    const int tid = threadIdx.x;
    const int lane = tid & 31;
    const int warp = tid >> 5;
    const int wm = warp >> 1;
    const int wn = warp & 1;
    const int g  = lane >> 2;
    const int tg = lane & 3;
    const int m0 = blockIdx.y * BM;
    const int n0 = blockIdx.x * BN;

    const uint32_t* Apl[4];
    const uint32_t* Bpl[4];
    int a_row0;
    if (PHASE == 0) {
        Apl[0] = g_cX_hr; Apl[1] = g_cX_lr; Apl[2] = g_cX_hi; Apl[3] = g_cX_li;
        Bpl[0] = g_cWu_hr; Bpl[1] = g_cWu_lr; Bpl[2] = g_cWu_hi; Bpl[3] = g_cWu_li;
        a_row0 = m_base;
    } else {
        Apl[0] = g_cUp_hr; Apl[1] = g_cUp_lr; Apl[2] = g_cUp_hi; Apl[3] = g_cUp_li;
        Bpl[0] = g_cWd_hr; Bpl[1] = g_cWd_lr; Bpl[2] = g_cWd_hi; Bpl[3] = g_cWd_li;
        a_row0 = 0;
    }
    constexpr int rw = KK / 2;   // global plane row length in words
    constexpr int NK = KK / BK;  // mainloop stages (compile-time)

    float accRe[2][4][4], accIm[2][4][4];
#pragma unroll
    for (int mi = 0; mi < 2; mi++)
#pragma unroll
        for (int ni = 0; ni < 4; ni++)
#pragma unroll
            for (int r = 0; r < 4; r++) { accRe[mi][ni][r] = 0.f; accIm[mi][ni][r] = 0.f; }

    // Stage loader: 3072 16B chunks / 256 threads = 12 each.
    auto load_stage = [&](int buf, int k0) {
        const int kw0 = k0 >> 1;
        const uint32_t sb = smem_b + (uint32_t)buf * STAGE_W * 4;
#pragma unroll
        for (int t = 0; t < 8; t++) {
            int c = tid + t * THREADS;       // A: 0..2047
            int p = c >> 9;
            int r = (c >> 2) & 127;
            int kc = c & 3;
            const uint32_t* src = Apl[p] + (size_t)(a_row0 + m0 + r) * rw + kw0 + kc * 4;
            int w = r * RW + ((kc ^ ((r >> 1) & 3)) << 2);
            cpasync16(sb + (uint32_t)(p * A_PL + w) * 4, src);
        }
#pragma unroll
        for (int t = 0; t < 4; t++) {
            int c = tid + t * THREADS;       // B: 0..1023
            int p = c >> 8;
            int r = (c >> 2) & 63;
            int kc = c & 3;
            const uint32_t* src = Bpl[p] + (size_t)(n0 + r) * rw + kw0 + kc * 4;
            int w = r * RW + ((kc ^ ((r >> 1) & 3)) << 2);
            cpasync16(sb + (uint32_t)(B_OFF + p * B_PL + w) * 4, src);
        }
        CP_COMMIT();
    };

    load_stage(0, 0);

#pragma unroll 2
    for (int it = 0; it < NK; it++) {
        // Single barrier per stage: publishes stage-it data (after cp_wait)
        // AND guarantees buf^1 reads from iteration it-1 are complete.
        cp_wait<0>();
        __syncthreads();
        if (it + 1 < NK) load_stage((it + 1) & 1, (it + 1) * BK);

        const int st = (it & 1) * STAGE_W;   // compile-time per unrolled body
        const int AHR = st, ALR = st + A_PL, AHI = st + 2 * A_PL, ALI = st + 3 * A_PL;
        const int BHR = st + B_OFF, BLR = BHR + B_PL, BHI = BHR + 2 * B_PL, BLI = BHR + 3 * B_PL;

#pragma unroll
        for (int ks = 0; ks < 2; ks++) {
            uint32_t Brh[4][2], Brl[4][2], Bih[4][2], Bil[4][2];
#pragma unroll
            for (int ni = 0; ni < 4; ni++) {
                const int rb = wn * 32 + ni * 8 + g;
                const int w0 = swz(rb, ks * 8 + tg);
                const int w1 = swz(rb, ks * 8 + tg + 4);
                Brh[ni][0] = s[BHR + w0]; Brh[ni][1] = s[BHR + w1];
                Brl[ni][0] = s[BLR + w0]; Brl[ni][1] = s[BLR + w1];
                Bih[ni][0] = s[BHI + w0]; Bih[ni][1] = s[BHI + w1];
                Bil[ni][0] = s[BLI + w0]; Bil[ni][1] = s[BLI + w1];
            }
            uint32_t Arh[2][4], Arl[2][4], Aih[2][4], Ail[2][4], nAih[2][4], nAil[2][4];
#pragma unroll
            for (int mi = 0; mi < 2; mi++) {
                const int r0 = wm * 32 + mi * 16 + g;
                const int r1 = r0 + 8;
                const int u0 = swz(r0, ks * 8 + tg);
                const int u1 = swz(r1, ks * 8 + tg);
                const int u2 = swz(r0, ks * 8 + tg + 4);
                const int u3 = swz(r1, ks * 8 + tg + 4);
                Arh[mi][0] = s[AHR + u0]; Arh[mi][1] = s[AHR + u1];
                Arh[mi][2] = s[AHR + u2]; Arh[mi][3] = s[AHR + u3];
                Arl[mi][0] = s[ALR + u0]; Arl[mi][1] = s[ALR + u1];
                Arl[mi][2] = s[ALR + u2]; Arl[mi][3] = s[ALR + u3];
                Aih[mi][0] = s[AHI + u0]; Aih[mi][1] = s[AHI + u1];
                Aih[mi][2] = s[AHI + u2]; Aih[mi][3] = s[AHI + u3];
                Ail[mi][0] = s[ALI + u0]; Ail[mi][1] = s[ALI + u1];
                Ail[mi][2] = s[ALI + u2]; Ail[mi][3] = s[ALI + u3];
#pragma unroll
                for (int r = 0; r < 4; r++) {
                    nAih[mi][r] = Aih[mi][r] ^ 0x80008000u;
                    nAil[mi][r] = Ail[mi][r] ^ 0x80008000u;
                }
            }
#pragma unroll
            for (int mi = 0; mi < 2; mi++) {
#pragma unroll
                for (int ni = 0; ni < 4; ni++) {
                    mma16816(accRe[mi][ni], Arh[mi],  Brh[ni]);
                    mma16816(accRe[mi][ni], Arh[mi],  Brl[ni]);
                    mma16816(accRe[mi][ni], Arl[mi],  Brh[ni]);
                    mma16816(accRe[mi][ni], nAih[mi], Bih[ni]);
                    mma16816(accRe[mi][ni], nAih[mi], Bil[ni]);
                    mma16816(accRe[mi][ni], nAil[mi], Bih[ni]);
                    mma16816(accIm[mi][ni], Arh[mi],  Bih[ni]);
                    mma16816(accIm[mi][ni], Arh[mi],  Bil[ni]);
                    mma16816(accIm[mi][ni], Arl[mi],  Bih[ni]);
                    mma16816(accIm[mi][ni], Aih[mi],  Brh[ni]);
                    mma16816(accIm[mi][ni], Aih[mi],  Brl[ni]);
                    mma16816(accIm[mi][ni], Ail[mi],  Brh[ni]);
                }
            }
        }
    }

    // ---- epilogue ----
    const bool bias_ok = (PHASE != 0) || ((size_t)n0 + BN <= bias_lim);
#pragma unroll
    for (int mi = 0; mi < 2; mi++) {
#pragma unroll
        for (int ni = 0; ni < 4; ni++) {
            const int col = n0 + wn * 32 + ni * 8 + 2 * tg;   // even
#pragma unroll
            for (int h = 0; h < 2; h++) {
                const int row = m0 + wm * 32 + mi * 16 + g + h * 8;
                float re0 = accRe[mi][ni][2 * h], re1 = accRe[mi][ni][2 * h + 1];
                float im0 = accIm[mi][ni][2 * h], im1 = accIm[mi][ni][2 * h + 1];
                if (PHASE == 0) {
                    float br0 = 0.f, br1 = 0.f, bi0 = 0.f, bi1 = 0.f, mb0 = 0.f, mb1 = 0.f;
                    if (bias_ok) {
                        br0 = bias_re[col]; br1 = bias_re[col + 1];
                        bi0 = bias_im[col]; bi1 = bias_im[col + 1];
                        mb0 = mrb[col];     mb1 = mrb[col + 1];
                    }
                    re0 += br0; im0 += bi0; re1 += br1; im1 += bi1;
                    float mag0 = sqrtf(re0 * re0 + im0 * im0);
                    float mag1 = sqrtf(re1 * re1 + im1 * im1);
                    float s0 = fmaxf(mag0 + mb0, 0.f) / (mag0 + LN_EPS);
                    float s1 = fmaxf(mag1 + mb1, 0.f) / (mag1 + LN_EPS);
                    re0 *= s0; im0 *= s0; re1 *= s1; im1 *= s1;
                    const size_t wo = (size_t)row * (NN / 2) + (col >> 1);
                    split2(re0, re1, g_cUp_hr[wo], g_cUp_lr[wo]);
                    split2(im0, im1, g_cUp_hi[wo], g_cUp_li[wo]);
                } else {
                    const size_t off = (size_t)row * NN + col;
                    *reinterpret_cast<float2*>(g_dn_re + off) = make_float2(re0, re1);
                    *reinterpret_cast<float2*>(g_dn_im + off) = make_float2(im0, im1);
                }
            }
        }
    }
}

// Complex LayerNorm over D + residual, one block per (chunk-local) token row.
template <int OUT_MODE>
__global__ void __launch_bounds__(256)
ln_res_kernel(const float* __restrict__ xr, const float* __restrict__ xi,
              const float* __restrict__ gr, const float* __restrict__ gi,
              const float* __restrict__ br, const float* __restrict__ bi,
              float* __restrict__ out, int m_base,
              size_t x_lim, size_t p_lim, size_t out_cap) {
    const int m = blockIdx.x;
    const size_t base = (size_t)m * CD;
    const size_t gbase = (size_t)(m_base + m) * CD;
    const int tid = threadIdx.x;
    const bool x_ok = (gbase + CD) <= x_lim;
    const bool p_ok = (size_t)CD <= p_lim;

    float sr = 0.f, si = 0.f, sq = 0.f;
    for (int d = tid; d < CD; d += 256) {
        float r = g_dn_re[base + d];
        float q = g_dn_im[base + d];
        sr += r; si += q; sq += r * r + q * q;
    }
    __shared__ float red0[256], red1[256], red2[256];
    red0[tid] = sr; red1[tid] = si; red2[tid] = sq;
    __syncthreads();
    for (int st = 128; st > 0; st >>= 1) {
        if (tid < st) {
            red0[tid] += red0[tid + st];
            red1[tid] += red1[tid + st];
            red2[tid] += red2[tid + st];
        }
        __syncthreads();
    }
    const float inv_d = 1.f / (float)CD;
    const float mur = red0[0] * inv_d;
    const float mui = red1[0] * inv_d;
    const float var = red2[0] * inv_d - (mur * mur + mui * mui);
    const float rstd = rsqrtf(var + LN_EPS);

    for (int d = tid; d < CD; d += 256) {
        float zr = (g_dn_re[base + d] - mur) * rstd;
        float zi = (g_dn_im[base + d] - mui) * rstd;
        float g_r = p_ok ? gr[d] : 1.f;
        float g_i = p_ok ? gi[d] : 0.f;
        float b_r = p_ok ? br[d] : 0.f;
        float b_i = p_ok ? bi[d] : 0.f;
        float xre = x_ok ? xr[gbase + d] : 0.f;
        float xim = x_ok ? xi[gbase + d] : 0.f;
        float o_r = g_r * zr - g_i * zi + b_r + xre;
        float o_i = g_r * zi + g_i * zr + b_i + xim;
        if (OUT_MODE == 0) {
            const size_t fo = gbase + d;
            if (fo < out_cap) out[fo] = o_r;
        } else {
            const size_t fo = 2 * (gbase + d);
            if (fo + 1 < out_cap) { out[fo] = o_r; out[fo + 1] = o_i; }
        }
    }
}

// ---------------- host-side binding ----------------
static bool match_sig(const int* s, const long long* want, long long scale) {
    for (int i = 0; i < 13; i++)
        if ((long long)s[i] != want[i] * scale) return false;
    return true;
}

extern "C" void kernel_launch(void* const* d_in, const int* in_sizes, int n_in,
                              void* d_out, int out_size) {
    if (n_in < 13) return;
    for (int i = 0; i < 13; i++) if (d_in[i] == nullptr) return;

    static const long long SIG_DICT[13] =
        {16777216,16777216,16777216,16777216,8192,8192,8192,
         16777216,16777216,2048,2048,2048,2048};
    static const long long SIG_ALPHA[13] =
        {16777216,16777216,16777216,16777216,8192,8192,
         2048,2048,2048,2048,8192,16777216,16777216};

    int order = 0;
    long long unit = 1;
    if (match_sig(in_sizes, SIG_DICT, 1))       { order = 0; unit = 1; }
    else if (match_sig(in_sizes, SIG_ALPHA, 1)) { order = 1; unit = 1; }
    else if (match_sig(in_sizes, SIG_DICT, 4))  { order = 0; unit = 4; }
    else if (match_sig(in_sizes, SIG_ALPHA, 4)) { order = 1; unit = 4; }

    const float *x_re, *x_im, *Wup_re, *Wup_im, *bias_re, *bias_im, *mrb;
    const float *Wd_re, *Wd_im, *g_re, *g_im, *be_re, *be_im;
    size_t sz[13];
    for (int i = 0; i < 13; i++) sz[i] = (size_t)((long long)in_sizes[i] / unit);
    size_t x_lim, wup_lim, wd_lim, bias_lim, ln_lim;

    if (order == 0) {
        x_re   = (const float*)d_in[0];  x_im   = (const float*)d_in[1];
        Wup_re = (const float*)d_in[2];  Wup_im = (const float*)d_in[3];
        bias_re = (const float*)d_in[4]; bias_im = (const float*)d_in[5];
        mrb    = (const float*)d_in[6];
        Wd_re  = (const float*)d_in[7];  Wd_im  = (const float*)d_in[8];
        g_re   = (const float*)d_in[9];  g_im   = (const float*)d_in[10];
        be_re  = (const float*)d_in[11]; be_im  = (const float*)d_in[12];
        x_lim = sz[0] < sz[1] ? sz[0] : sz[1];
        wup_lim = sz[2] < sz[3] ? sz[2] : sz[3];
        bias_lim = sz[4] < sz[5] ? sz[4] : sz[5];
        if (sz[6] < bias_lim) bias_lim = sz[6];
        wd_lim = sz[7] < sz[8] ? sz[7] : sz[8];
        ln_lim = sz[9];
        for (int i = 10; i <= 12; i++) if (sz[i] < ln_lim) ln_lim = sz[i];
    } else {
        Wd_im  = (const float*)d_in[0];  Wd_re  = (const float*)d_in[1];
        Wup_im = (const float*)d_in[2];  Wup_re = (const float*)d_in[3];
        bias_im = (const float*)d_in[4]; bias_re = (const float*)d_in[5];
        be_im  = (const float*)d_in[6];  be_re  = (const float*)d_in[7];
        g_im   = (const float*)d_in[8];  g_re   = (const float*)d_in[9];
        mrb    = (const float*)d_in[10];
        x_im   = (const float*)d_in[11]; x_re   = (const float*)d_in[12];
        wd_lim = sz[0] < sz[1] ? sz[0] : sz[1];
        wup_lim = sz[2] < sz[3] ? sz[2] : sz[3];
        bias_lim = sz[4] < sz[5] ? sz[4] : sz[5];
        if (sz[10] < bias_lim) bias_lim = sz[10];
        ln_lim = sz[6];
        for (int i = 7; i <= 9; i++) if (sz[i] < ln_lim) ln_lim = sz[i];
        x_lim = sz[11] < sz[12] ? sz[11] : sz[12];
    }

    const bool real_only = ((long long)out_size == 16777216LL);
    const size_t out_cap = (size_t)(long long)out_size;

    static bool attr_done = false;
    if (!attr_done) {
        cudaFuncSetAttribute((const void*)cgemm_nt<0, CD, CF>,
                             cudaFuncAttributeMaxDynamicSharedMemorySize, SMEM_BYTES);
        cudaFuncSetAttribute((const void*)cgemm_nt<1, CF, CD>,
                             cudaFuncAttributeMaxDynamicSharedMemorySize, SMEM_BYTES);
        attr_done = true;
    }

    // ---- pre-convert x, Wup, Wdown to packed bf16 hi/lo planes ----
    uint32_t *cx0, *cx1, *cx2, *cx3, *cu0, *cu1, *cu2, *cu3, *cd0, *cd1, *cd2, *cd3;
    cudaGetSymbolAddress((void**)&cx0, g_cX_hr);  cudaGetSymbolAddress((void**)&cx1, g_cX_lr);
    cudaGetSymbolAddress((void**)&cx2, g_cX_hi);  cudaGetSymbolAddress((void**)&cx3, g_cX_li);
    cudaGetSymbolAddress((void**)&cu0, g_cWu_hr); cudaGetSymbolAddress((void**)&cu1, g_cWu_lr);
    cudaGetSymbolAddress((void**)&cu2, g_cWu_hi); cudaGetSymbolAddress((void**)&cu3, g_cWu_li);
    cudaGetSymbolAddress((void**)&cd0, g_cWd_hr); cudaGetSymbolAddress((void**)&cd1, g_cWd_lr);
    cudaGetSymbolAddress((void**)&cd2, g_cWd_hi); cudaGetSymbolAddress((void**)&cd3, g_cWd_li);

    {
        int gx = (int)((XW + 255) / 256);
        conv_kernel<<<gx, 256>>>(x_re, x_im, cx0, cx1, cx2, cx3, XW, x_lim);
        int gw = (int)((WW + 255) / 256);
        conv_kernel<<<gw, 256>>>(Wup_re, Wup_im, cu0, cu1, cu2, cu3, WW, wup_lim);
        conv_kernel<<<gw, 256>>>(Wd_re, Wd_im, cd0, cd1, cd2, cd3, WW, wd_lim);
    }

    for (int c = 0; c < NCHUNKS; c++) {
        const int mb = c * MCHUNK;
        dim3 g1(CF / BN, MCHUNK / BM);
        cgemm_nt<0, CD, CF><<<g1, THREADS, SMEM_BYTES>>>(bias_re, bias_im, mrb,
                                                         mb, bias_lim);
        dim3 g2(CD / BN, MCHUNK / BM);
        cgemm_nt<1, CF, CD><<<g2, THREADS, SMEM_BYTES>>>(nullptr, nullptr, nullptr,
                                                         mb, 0);
        if (real_only) {
            ln_res_kernel<0><<<MCHUNK, 256>>>(x_re, x_im, g_re, g_im,
                                              be_re, be_im, (float*)d_out, mb,
                                              x_lim, ln_lim, out_cap);
        } else {
            ln_res_kernel<1><<<MCHUNK, 256>>>(x_re, x_im, g_re, g_im,
                                              be_re, be_im, (float*)d_out, mb,
                                              x_lim, ln_lim, out_cap);
        }
    }
}

// round 13
// speedup vs baseline: 1.0336x; 1.0336x over previous
#include <cuda_runtime.h>
#include <cuda_bf16.h>
#include <math.h>
#include <stdint.h>

#define LN_EPS 1e-5f

// Problem constants
constexpr int CB = 4, CS = 2048, CD = 2048, CF = 8192;
constexpr int CM = CB * CS;
constexpr int MCHUNK = 2048;
constexpr int NCHUNKS = CM / MCHUNK;

// GEMM tiling
constexpr int BM = 128, BN = 64, BK = 32;
constexpr int THREADS = 256;     // 8 warps: 4 (M) x 2 (N)
constexpr int RW = 16;           // smem row pitch in words (swizzled, no pad)

// Smem layout (words): per stage, 4 A planes then 4 B planes.
constexpr int A_PL = BM * RW;                // 2048 words
constexpr int B_PL = BN * RW;                // 1024 words
constexpr int B_OFF = 4 * A_PL;              // 8192
constexpr int STAGE_W = 4 * A_PL + 4 * B_PL; // 12288 words
constexpr int SMEM_BYTES = 2 * STAGE_W * 4;  // 98304 B -> 2 CTAs/SM

// ---- device-global scratch: packed bf16x2 hi/lo planes (word = k,k+1) ----
constexpr size_t XW = (size_t)CM * CD / 2;
constexpr size_t WW = (size_t)CF * CD / 2;
constexpr size_t UW = (size_t)MCHUNK * CF / 2;
__device__ __align__(16) uint32_t g_cX_hr[XW], g_cX_lr[XW], g_cX_hi[XW], g_cX_li[XW];
__device__ __align__(16) uint32_t g_cWu_hr[WW], g_cWu_lr[WW], g_cWu_hi[WW], g_cWu_li[WW];
__device__ __align__(16) uint32_t g_cWd_hr[WW], g_cWd_lr[WW], g_cWd_hi[WW], g_cWd_li[WW];
__device__ __align__(16) uint32_t g_cUp_hr[UW], g_cUp_lr[UW], g_cUp_hi[UW], g_cUp_li[UW];
__device__ __align__(16) float g_dn_re[(size_t)MCHUNK * CD];
__device__ __align__(16) float g_dn_im[(size_t)MCHUNK * CD];

// Split two fp32 into packed bf16 hi / lo words
__device__ __forceinline__ void split2(float x, float y, uint32_t& hi, uint32_t& lo) {
    __nv_bfloat16 xh = __float2bfloat16_rn(x);
    __nv_bfloat16 yh = __float2bfloat16_rn(y);
    float xr = x - __bfloat162float(xh);
    float yr = y - __bfloat162float(yh);
    __nv_bfloat16 xl = __float2bfloat16_rn(xr);
    __nv_bfloat16 yl = __float2bfloat16_rn(yr);
    hi = (uint32_t)__bfloat16_as_ushort(xh) | ((uint32_t)__bfloat16_as_ushort(yh) << 16);
    lo = (uint32_t)__bfloat16_as_ushort(xl) | ((uint32_t)__bfloat16_as_ushort(yl) << 16);
}

__device__ __forceinline__ void mma16816(float* c, const uint32_t* a, const uint32_t* b) {
    asm volatile(
        "mma.sync.aligned.m16n8k16.row.col.f32.bf16.bf16.f32 "
        "{%0,%1,%2,%3}, {%4,%5,%6,%7}, {%8,%9}, {%0,%1,%2,%3};\n"
        : "+f"(c[0]), "+f"(c[1]), "+f"(c[2]), "+f"(c[3])
        : "r"(a[0]), "r"(a[1]), "r"(a[2]), "r"(a[3]), "r"(b[0]), "r"(b[1]));
}

__device__ __forceinline__ void cpasync16(uint32_t smem_bytes_addr, const void* g) {
    asm volatile("cp.async.cg.shared.global [%0], [%1], 16;\n"
                 :: "r"(smem_bytes_addr), "l"(g));
}
#define CP_COMMIT() asm volatile("cp.async.commit_group;\n")
template <int N>
__device__ __forceinline__ void cp_wait() {
    asm volatile("cp.async.wait_group %0;\n" :: "n"(N));
}

// Swizzled word index within a plane: row pitch 16 words, 16B-chunk XOR.
__device__ __forceinline__ int swz(int row, int kb) {
    return row * RW + ((((kb >> 2) ^ ((row >> 1) & 3)) << 2) | (kb & 3));
}

// Pre-conversion: fp32 planar -> packed bf16x2 hi/lo planes.
__global__ void __launch_bounds__(256)
conv_kernel(const float* __restrict__ re, const float* __restrict__ im,
            uint32_t* __restrict__ hr, uint32_t* __restrict__ lr,
            uint32_t* __restrict__ hi_, uint32_t* __restrict__ li,
            size_t nwords, size_t lim) {
    size_t i = (size_t)blockIdx.x * 256 + threadIdx.x;
    if (i >= nwords) return;
    size_t e = 2 * i;
    float r0 = 0.f, r1 = 0.f, q0 = 0.f, q1 = 0.f;
    if (e + 2 <= lim) {
        float2 v = *reinterpret_cast<const float2*>(re + e);
        float2 w = *reinterpret_cast<const float2*>(im + e);
        r0 = v.x; r1 = v.y; q0 = w.x; q1 = w.y;
    }
    split2(r0, r1, hr[i], lr[i]);
    split2(q0, q1, hi_[i], li[i]);
}

// Complex NT GEMM: R10 pipeline structure (load-before-wait, two barriers),
// compile-time K/N, swizzled smem, 2 CTAs/SM.
// PHASE 0: A = g_cX (rows m_base+..), B = g_cWu, epi = bias+modrelu -> g_cUp
// PHASE 1: A = g_cUp (chunk-local), B = g_cWd, epi = plain -> g_dn
template <int PHASE, int KK, int NN>
__global__ void __launch_bounds__(THREADS, 2)
cgemm_nt(const float* __restrict__ bias_re, const float* __restrict__ bias_im,
         const float* __restrict__ mrb,
         int m_base, size_t bias_lim) {
    extern __shared__ uint32_t s[];
    const uint32_t smem_b = (uint32_t)__cvta_generic_to_shared(s);

    const int tid = threadIdx.x;
    const int lane = tid & 31;
    const int warp = tid >> 5;
    const int wm = warp >> 1;
    const int wn = warp & 1;
    const int g  = lane >> 2;
    const int tg = lane & 3;
    const int m0 = blockIdx.y * BM;
    const int n0 = blockIdx.x * BN;

    const uint32_t* Apl[4];
    const uint32_t* Bpl[4];
    int a_row0;
    if (PHASE == 0) {
        Apl[0] = g_cX_hr; Apl[1] = g_cX_lr; Apl[2] = g_cX_hi; Apl[3] = g_cX_li;
        Bpl[0] = g_cWu_hr; Bpl[1] = g_cWu_lr; Bpl[2] = g_cWu_hi; Bpl[3] = g_cWu_li;
        a_row0 = m_base;
    } else {
        Apl[0] = g_cUp_hr; Apl[1] = g_cUp_lr; Apl[2] = g_cUp_hi; Apl[3] = g_cUp_li;
        Bpl[0] = g_cWd_hr; Bpl[1] = g_cWd_lr; Bpl[2] = g_cWd_hi; Bpl[3] = g_cWd_li;
        a_row0 = 0;
    }
    constexpr int rw = KK / 2;   // global plane row length in words
    constexpr int NK = KK / BK;  // mainloop stages (compile-time)

    float accRe[2][4][4], accIm[2][4][4];
#pragma unroll
    for (int mi = 0; mi < 2; mi++)
#pragma unroll
        for (int ni = 0; ni < 4; ni++)
#pragma unroll
            for (int r = 0; r < 4; r++) { accRe[mi][ni][r] = 0.f; accIm[mi][ni][r] = 0.f; }

    // Stage loader: 3072 16B chunks / 256 threads = 12 each.
    auto load_stage = [&](int buf, int k0) {
        const int kw0 = k0 >> 1;
        const uint32_t sb = smem_b + (uint32_t)buf * STAGE_W * 4;
#pragma unroll
        for (int t = 0; t < 8; t++) {
            int c = tid + t * THREADS;       // A: 0..2047
            int p = c >> 9;
            int r = (c >> 2) & 127;
            int kc = c & 3;
            const uint32_t* src = Apl[p] + (size_t)(a_row0 + m0 + r) * rw + kw0 + kc * 4;
            int w = r * RW + ((kc ^ ((r >> 1) & 3)) << 2);
            cpasync16(sb + (uint32_t)(p * A_PL + w) * 4, src);
        }
#pragma unroll
        for (int t = 0; t < 4; t++) {
            int c = tid + t * THREADS;       // B: 0..1023
            int p = c >> 8;
            int r = (c >> 2) & 63;
            int kc = c & 3;
            const uint32_t* src = Bpl[p] + (size_t)(n0 + r) * rw + kw0 + kc * 4;
            int w = r * RW + ((kc ^ ((r >> 1) & 3)) << 2);
            cpasync16(sb + (uint32_t)(B_OFF + p * B_PL + w) * 4, src);
        }
        CP_COMMIT();
    };

    load_stage(0, 0);

#pragma unroll 2
    for (int it = 0; it < NK; it++) {
        // R10 structure: issue next-stage loads FIRST, then wait on current —
        // keeps the memory pipe busy across the barrier.
        if (it + 1 < NK) {
            load_stage((it + 1) & 1, (it + 1) * BK);
            cp_wait<1>();
        } else {
            cp_wait<0>();
        }
        __syncthreads();

        const int st = (it & 1) * STAGE_W;   // compile-time per unrolled body
        const int AHR = st, ALR = st + A_PL, AHI = st + 2 * A_PL, ALI = st + 3 * A_PL;
        const int BHR = st + B_OFF, BLR = BHR + B_PL, BHI = BHR + 2 * B_PL, BLI = BHR + 3 * B_PL;

#pragma unroll
        for (int ks = 0; ks < 2; ks++) {
            uint32_t Brh[4][2], Brl[4][2], Bih[4][2], Bil[4][2];
#pragma unroll
            for (int ni = 0; ni < 4; ni++) {
                const int rb = wn * 32 + ni * 8 + g;
                const int w0 = swz(rb, ks * 8 + tg);
                const int w1 = swz(rb, ks * 8 + tg + 4);
                Brh[ni][0] = s[BHR + w0]; Brh[ni][1] = s[BHR + w1];
                Brl[ni][0] = s[BLR + w0]; Brl[ni][1] = s[BLR + w1];
                Bih[ni][0] = s[BHI + w0]; Bih[ni][1] = s[BHI + w1];
                Bil[ni][0] = s[BLI + w0]; Bil[ni][1] = s[BLI + w1];
            }
            uint32_t Arh[2][4], Arl[2][4], Aih[2][4], Ail[2][4], nAih[2][4], nAil[2][4];
#pragma unroll
            for (int mi = 0; mi < 2; mi++) {
                const int r0 = wm * 32 + mi * 16 + g;
                const int r1 = r0 + 8;
                const int u0 = swz(r0, ks * 8 + tg);
                const int u1 = swz(r1, ks * 8 + tg);
                const int u2 = swz(r0, ks * 8 + tg + 4);
                const int u3 = swz(r1, ks * 8 + tg + 4);
                Arh[mi][0] = s[AHR + u0]; Arh[mi][1] = s[AHR + u1];
                Arh[mi][2] = s[AHR + u2]; Arh[mi][3] = s[AHR + u3];
                Arl[mi][0] = s[ALR + u0]; Arl[mi][1] = s[ALR + u1];
                Arl[mi][2] = s[ALR + u2]; Arl[mi][3] = s[ALR + u3];
                Aih[mi][0] = s[AHI + u0]; Aih[mi][1] = s[AHI + u1];
                Aih[mi][2] = s[AHI + u2]; Aih[mi][3] = s[AHI + u3];
                Ail[mi][0] = s[ALI + u0]; Ail[mi][1] = s[ALI + u1];
                Ail[mi][2] = s[ALI + u2]; Ail[mi][3] = s[ALI + u3];
#pragma unroll
                for (int r = 0; r < 4; r++) {
                    nAih[mi][r] = Aih[mi][r] ^ 0x80008000u;
                    nAil[mi][r] = Ail[mi][r] ^ 0x80008000u;
                }
            }
#pragma unroll
            for (int mi = 0; mi < 2; mi++) {
#pragma unroll
                for (int ni = 0; ni < 4; ni++) {
                    mma16816(accRe[mi][ni], Arh[mi],  Brh[ni]);
                    mma16816(accRe[mi][ni], Arh[mi],  Brl[ni]);
                    mma16816(accRe[mi][ni], Arl[mi],  Brh[ni]);
                    mma16816(accRe[mi][ni], nAih[mi], Bih[ni]);
                    mma16816(accRe[mi][ni], nAih[mi], Bil[ni]);
                    mma16816(accRe[mi][ni], nAil[mi], Bih[ni]);
                    mma16816(accIm[mi][ni], Arh[mi],  Bih[ni]);
                    mma16816(accIm[mi][ni], Arh[mi],  Bil[ni]);
                    mma16816(accIm[mi][ni], Arl[mi],  Bih[ni]);
                    mma16816(accIm[mi][ni], Aih[mi],  Brh[ni]);
                    mma16816(accIm[mi][ni], Aih[mi],  Brl[ni]);
                    mma16816(accIm[mi][ni], Ail[mi],  Brh[ni]);
                }
            }
        }
        __syncthreads();
    }

    // ---- epilogue ----
    const bool bias_ok = (PHASE != 0) || ((size_t)n0 + BN <= bias_lim);
#pragma unroll
    for (int mi = 0; mi < 2; mi++) {
#pragma unroll
        for (int ni = 0; ni < 4; ni++) {
            const int col = n0 + wn * 32 + ni * 8 + 2 * tg;   // even
#pragma unroll
            for (int h = 0; h < 2; h++) {
                const int row = m0 + wm * 32 + mi * 16 + g + h * 8;
                float re0 = accRe[mi][ni][2 * h], re1 = accRe[mi][ni][2 * h + 1];
                float im0 = accIm[mi][ni][2 * h], im1 = accIm[mi][ni][2 * h + 1];
                if (PHASE == 0) {
                    float br0 = 0.f, br1 = 0.f, bi0 = 0.f, bi1 = 0.f, mb0 = 0.f, mb1 = 0.f;
                    if (bias_ok) {
                        br0 = bias_re[col]; br1 = bias_re[col + 1];
                        bi0 = bias_im[col]; bi1 = bias_im[col + 1];
                        mb0 = mrb[col];     mb1 = mrb[col + 1];
                    }
                    re0 += br0; im0 += bi0; re1 += br1; im1 += bi1;
                    float mag0 = sqrtf(re0 * re0 + im0 * im0);
                    float mag1 = sqrtf(re1 * re1 + im1 * im1);
                    float s0 = fmaxf(mag0 + mb0, 0.f) / (mag0 + LN_EPS);
                    float s1 = fmaxf(mag1 + mb1, 0.f) / (mag1 + LN_EPS);
                    re0 *= s0; im0 *= s0; re1 *= s1; im1 *= s1;
                    const size_t wo = (size_t)row * (NN / 2) + (col >> 1);
                    split2(re0, re1, g_cUp_hr[wo], g_cUp_lr[wo]);
                    split2(im0, im1, g_cUp_hi[wo], g_cUp_li[wo]);
                } else {
                    const size_t off = (size_t)row * NN + col;
                    *reinterpret_cast<float2*>(g_dn_re + off) = make_float2(re0, re1);
                    *reinterpret_cast<float2*>(g_dn_im + off) = make_float2(im0, im1);
                }
            }
        }
    }
}

// Complex LayerNorm over D + residual, one block per (chunk-local) token row.
template <int OUT_MODE>
__global__ void __launch_bounds__(256)
ln_res_kernel(const float* __restrict__ xr, const float* __restrict__ xi,
              const float* __restrict__ gr, const float* __restrict__ gi,
              const float* __restrict__ br, const float* __restrict__ bi,
              float* __restrict__ out, int m_base,
              size_t x_lim, size_t p_lim, size_t out_cap) {
    const int m = blockIdx.x;
    const size_t base = (size_t)m * CD;
    const size_t gbase = (size_t)(m_base + m) * CD;
    const int tid = threadIdx.x;
    const bool x_ok = (gbase + CD) <= x_lim;
    const bool p_ok = (size_t)CD <= p_lim;

    float sr = 0.f, si = 0.f, sq = 0.f;
    for (int d = tid; d < CD; d += 256) {
        float r = g_dn_re[base + d];
        float q = g_dn_im[base + d];
        sr += r; si += q; sq += r * r + q * q;
    }
    __shared__ float red0[256], red1[256], red2[256];
    red0[tid] = sr; red1[tid] = si; red2[tid] = sq;
    __syncthreads();
    for (int st = 128; st > 0; st >>= 1) {
        if (tid < st) {
            red0[tid] += red0[tid + st];
            red1[tid] += red1[tid + st];
            red2[tid] += red2[tid + st];
        }
        __syncthreads();
    }
    const float inv_d = 1.f / (float)CD;
    const float mur = red0[0] * inv_d;
    const float mui = red1[0] * inv_d;
    const float var = red2[0] * inv_d - (mur * mur + mui * mui);
    const float rstd = rsqrtf(var + LN_EPS);

    for (int d = tid; d < CD; d += 256) {
        float zr = (g_dn_re[base + d] - mur) * rstd;
        float zi = (g_dn_im[base + d] - mui) * rstd;
        float g_r = p_ok ? gr[d] : 1.f;
        float g_i = p_ok ? gi[d] : 0.f;
        float b_r = p_ok ? br[d] : 0.f;
        float b_i = p_ok ? bi[d] : 0.f;
        float xre = x_ok ? xr[gbase + d] : 0.f;
        float xim = x_ok ? xi[gbase + d] : 0.f;
        float o_r = g_r * zr - g_i * zi + b_r + xre;
        float o_i = g_r * zi + g_i * zr + b_i + xim;
        if (OUT_MODE == 0) {
            const size_t fo = gbase + d;
            if (fo < out_cap) out[fo] = o_r;
        } else {
            const size_t fo = 2 * (gbase + d);
            if (fo + 1 < out_cap) { out[fo] = o_r; out[fo + 1] = o_i; }
        }
    }
}

// ---------------- host-side binding ----------------
static bool match_sig(const int* s, const long long* want, long long scale) {
    for (int i = 0; i < 13; i++)
        if ((long long)s[i] != want[i] * scale) return false;
    return true;
}

extern "C" void kernel_launch(void* const* d_in, const int* in_sizes, int n_in,
                              void* d_out, int out_size) {
    if (n_in < 13) return;
    for (int i = 0; i < 13; i++) if (d_in[i] == nullptr) return;

    static const long long SIG_DICT[13] =
        {16777216,16777216,16777216,16777216,8192,8192,8192,
         16777216,16777216,2048,2048,2048,2048};
    static const long long SIG_ALPHA[13] =
        {16777216,16777216,16777216,16777216,8192,8192,
         2048,2048,2048,2048,8192,16777216,16777216};

    int order = 0;
    long long unit = 1;
    if (match_sig(in_sizes, SIG_DICT, 1))       { order = 0; unit = 1; }
    else if (match_sig(in_sizes, SIG_ALPHA, 1)) { order = 1; unit = 1; }
    else if (match_sig(in_sizes, SIG_DICT, 4))  { order = 0; unit = 4; }
    else if (match_sig(in_sizes, SIG_ALPHA, 4)) { order = 1; unit = 4; }

    const float *x_re, *x_im, *Wup_re, *Wup_im, *bias_re, *bias_im, *mrb;
    const float *Wd_re, *Wd_im, *g_re, *g_im, *be_re, *be_im;
    size_t sz[13];
    for (int i = 0; i < 13; i++) sz[i] = (size_t)((long long)in_sizes[i] / unit);
    size_t x_lim, wup_lim, wd_lim, bias_lim, ln_lim;

    if (order == 0) {
        x_re   = (const float*)d_in[0];  x_im   = (const float*)d_in[1];
        Wup_re = (const float*)d_in[2];  Wup_im = (const float*)d_in[3];
        bias_re = (const float*)d_in[4]; bias_im = (const float*)d_in[5];
        mrb    = (const float*)d_in[6];
        Wd_re  = (const float*)d_in[7];  Wd_im  = (const float*)d_in[8];
        g_re   = (const float*)d_in[9];  g_im   = (const float*)d_in[10];
        be_re  = (const float*)d_in[11]; be_im  = (const float*)d_in[12];
        x_lim = sz[0] < sz[1] ? sz[0] : sz[1];
        wup_lim = sz[2] < sz[3] ? sz[2] : sz[3];
        bias_lim = sz[4] < sz[5] ? sz[4] : sz[5];
        if (sz[6] < bias_lim) bias_lim = sz[6];
        wd_lim = sz[7] < sz[8] ? sz[7] : sz[8];
        ln_lim = sz[9];
        for (int i = 10; i <= 12; i++) if (sz[i] < ln_lim) ln_lim = sz[i];
    } else {
        Wd_im  = (const float*)d_in[0];  Wd_re  = (const float*)d_in[1];
        Wup_im = (const float*)d_in[2];  Wup_re = (const float*)d_in[3];
        bias_im = (const float*)d_in[4]; bias_re = (const float*)d_in[5];
        be_im  = (const float*)d_in[6];  be_re  = (const float*)d_in[7];
        g_im   = (const float*)d_in[8];  g_re   = (const float*)d_in[9];
        mrb    = (const float*)d_in[10];
        x_im   = (const float*)d_in[11]; x_re   = (const float*)d_in[12];
        wd_lim = sz[0] < sz[1] ? sz[0] : sz[1];
        wup_lim = sz[2] < sz[3] ? sz[2] : sz[3];
        bias_lim = sz[4] < sz[5] ? sz[4] : sz[5];
        if (sz[10] < bias_lim) bias_lim = sz[10];
        ln_lim = sz[6];
        for (int i = 7; i <= 9; i++) if (sz[i] < ln_lim) ln_lim = sz[i];
        x_lim = sz[11] < sz[12] ? sz[11] : sz[12];
    }

    const bool real_only = ((long long)out_size == 16777216LL);
    const size_t out_cap = (size_t)(long long)out_size;

    static bool attr_done = false;
    if (!attr_done) {
        cudaFuncSetAttribute((const void*)cgemm_nt<0, CD, CF>,
                             cudaFuncAttributeMaxDynamicSharedMemorySize, SMEM_BYTES);
        cudaFuncSetAttribute((const void*)cgemm_nt<1, CF, CD>,
                             cudaFuncAttributeMaxDynamicSharedMemorySize, SMEM_BYTES);
        attr_done = true;
    }

    // ---- pre-convert x, Wup, Wdown to packed bf16 hi/lo planes ----
    uint32_t *cx0, *cx1, *cx2, *cx3, *cu0, *cu1, *cu2, *cu3, *cd0, *cd1, *cd2, *cd3;
    cudaGetSymbolAddress((void**)&cx0, g_cX_hr);  cudaGetSymbolAddress((void**)&cx1, g_cX_lr);
    cudaGetSymbolAddress((void**)&cx2, g_cX_hi);  cudaGetSymbolAddress((void**)&cx3, g_cX_li);
    cudaGetSymbolAddress((void**)&cu0, g_cWu_hr); cudaGetSymbolAddress((void**)&cu1, g_cWu_lr);
    cudaGetSymbolAddress((void**)&cu2, g_cWu_hi); cudaGetSymbolAddress((void**)&cu3, g_cWu_li);
    cudaGetSymbolAddress((void**)&cd0, g_cWd_hr); cudaGetSymbolAddress((void**)&cd1, g_cWd_lr);
    cudaGetSymbolAddress((void**)&cd2, g_cWd_hi); cudaGetSymbolAddress((void**)&cd3, g_cWd_li);

    {
        int gx = (int)((XW + 255) / 256);
        conv_kernel<<<gx, 256>>>(x_re, x_im, cx0, cx1, cx2, cx3, XW, x_lim);
        int gw = (int)((WW + 255) / 256);
        conv_kernel<<<gw, 256>>>(Wup_re, Wup_im, cu0, cu1, cu2, cu3, WW, wup_lim);
        conv_kernel<<<gw, 256>>>(Wd_re, Wd_im, cd0, cd1, cd2, cd3, WW, wd_lim);
    }

    for (int c = 0; c < NCHUNKS; c++) {
        const int mb = c * MCHUNK;
        dim3 g1(CF / BN, MCHUNK / BM);
        cgemm_nt<0, CD, CF><<<g1, THREADS, SMEM_BYTES>>>(bias_re, bias_im, mrb,
                                                         mb, bias_lim);
        dim3 g2(CD / BN, MCHUNK / BM);
        cgemm_nt<1, CF, CD><<<g2, THREADS, SMEM_BYTES>>>(nullptr, nullptr, nullptr,
                                                         mb, 0);
        if (real_only) {
            ln_res_kernel<0><<<MCHUNK, 256>>>(x_re, x_im, g_re, g_im,
                                              be_re, be_im, (float*)d_out, mb,
                                              x_lim, ln_lim, out_cap);
        } else {
            ln_res_kernel<1><<<MCHUNK, 256>>>(x_re, x_im, g_re, g_im,
                                              be_re, be_im, (float*)d_out, mb,
                                              x_lim, ln_lim, out_cap);
        }
    }
}

// round 14
// speedup vs baseline: 1.2164x; 1.1769x over previous
#include <cuda_runtime.h>
#include <cuda_bf16.h>
#include <math.h>
#include <stdint.h>

#define LN_EPS 1e-5f

// Problem constants
constexpr int CB = 4, CS = 2048, CD = 2048, CF = 8192;
constexpr int CM = CB * CS;
constexpr int MCHUNK = 2048;
constexpr int NCHUNKS = CM / MCHUNK;

// GEMM tiling
constexpr int BM = 128, BN = 64, BK = 32;
constexpr int THREADS = 256;     // 8 warps: 4 (M) x 2 (N)
constexpr int RW = 16;           // smem row pitch in words (swizzled, no pad)

// Smem layout (words): per stage, 4 A planes then 4 B planes.
constexpr int A_PL = BM * RW;                // 2048 words
constexpr int B_PL = BN * RW;                // 1024 words
constexpr int B_OFF = 4 * A_PL;              // 8192
constexpr int STAGE_W = 4 * A_PL + 4 * B_PL; // 12288 words
constexpr int SMEM_BYTES = 2 * STAGE_W * 4;  // 98304 B -> 2 CTAs/SM

// ---- device-global scratch: packed bf16x2 hi/lo planes (word = k,k+1) ----
constexpr size_t XW = (size_t)CM * CD / 2;
constexpr size_t WW = (size_t)CF * CD / 2;
constexpr size_t UW = (size_t)MCHUNK * CF / 2;
__device__ __align__(16) uint32_t g_cX_hr[XW], g_cX_lr[XW], g_cX_hi[XW], g_cX_li[XW];
__device__ __align__(16) uint32_t g_cWu_hr[WW], g_cWu_lr[WW], g_cWu_hi[WW], g_cWu_li[WW];
__device__ __align__(16) uint32_t g_cWd_hr[WW], g_cWd_lr[WW], g_cWd_hi[WW], g_cWd_li[WW];
__device__ __align__(16) uint32_t g_cUp_hr[UW], g_cUp_lr[UW], g_cUp_hi[UW], g_cUp_li[UW];
__device__ __align__(16) float g_dn_re[(size_t)MCHUNK * CD];
__device__ __align__(16) float g_dn_im[(size_t)MCHUNK * CD];

// Split two fp32 into packed bf16 hi / lo words
__device__ __forceinline__ void split2(float x, float y, uint32_t& hi, uint32_t& lo) {
    __nv_bfloat16 xh = __float2bfloat16_rn(x);
    __nv_bfloat16 yh = __float2bfloat16_rn(y);
    float xr = x - __bfloat162float(xh);
    float yr = y - __bfloat162float(yh);
    __nv_bfloat16 xl = __float2bfloat16_rn(xr);
    __nv_bfloat16 yl = __float2bfloat16_rn(yr);
    hi = (uint32_t)__bfloat16_as_ushort(xh) | ((uint32_t)__bfloat16_as_ushort(yh) << 16);
    lo = (uint32_t)__bfloat16_as_ushort(xl) | ((uint32_t)__bfloat16_as_ushort(yl) << 16);
}

__device__ __forceinline__ void mma16816(float* c, const uint32_t* a, const uint32_t* b) {
    asm volatile(
        "mma.sync.aligned.m16n8k16.row.col.f32.bf16.bf16.f32 "
        "{%0,%1,%2,%3}, {%4,%5,%6,%7}, {%8,%9}, {%0,%1,%2,%3};\n"
        : "+f"(c[0]), "+f"(c[1]), "+f"(c[2]), "+f"(c[3])
        : "r"(a[0]), "r"(a[1]), "r"(a[2]), "r"(a[3]), "r"(b[0]), "r"(b[1]));
}

#define LDSM4(r, addr) \
    asm volatile("ldmatrix.sync.aligned.m8n8.x4.shared.b16 {%0,%1,%2,%3}, [%4];" \
        : "=r"((r)[0]), "=r"((r)[1]), "=r"((r)[2]), "=r"((r)[3]) : "r"(addr))

__device__ __forceinline__ void cpasync16(uint32_t smem_bytes_addr, const void* g) {
    asm volatile("cp.async.cg.shared.global [%0], [%1], 16;\n"
                 :: "r"(smem_bytes_addr), "l"(g));
}
#define CP_COMMIT() asm volatile("cp.async.commit_group;\n")
template <int N>
__device__ __forceinline__ void cp_wait() {
    asm volatile("cp.async.wait_group %0;\n" :: "n"(N));
}

// Swizzled word index within a plane: row pitch 16 words, 16B-chunk XOR.
__device__ __forceinline__ int swz(int row, int kb) {
    return row * RW + ((((kb >> 2) ^ ((row >> 1) & 3)) << 2) | (kb & 3));
}

// Pre-conversion: fp32 planar -> packed bf16x2 hi/lo planes.
__global__ void __launch_bounds__(256)
conv_kernel(const float* __restrict__ re, const float* __restrict__ im,
            uint32_t* __restrict__ hr, uint32_t* __restrict__ lr,
            uint32_t* __restrict__ hi_, uint32_t* __restrict__ li,
            size_t nwords, size_t lim) {
    size_t i = (size_t)blockIdx.x * 256 + threadIdx.x;
    if (i >= nwords) return;
    size_t e = 2 * i;
    float r0 = 0.f, r1 = 0.f, q0 = 0.f, q1 = 0.f;
    if (e + 2 <= lim) {
        float2 v = *reinterpret_cast<const float2*>(re + e);
        float2 w = *reinterpret_cast<const float2*>(im + e);
        r0 = v.x; r1 = v.y; q0 = w.x; q1 = w.y;
    }
    split2(r0, r1, hr[i], lr[i]);
    split2(q0, q1, hi_[i], li[i]);
}

// Complex NT GEMM: R10 pipeline + A-side ldmatrix fragments (single change).
// PHASE 0: A = g_cX (rows m_base+..), B = g_cWu, epi = bias+modrelu -> g_cUp
// PHASE 1: A = g_cUp (chunk-local), B = g_cWd, epi = plain -> g_dn
template <int PHASE>
__global__ void __launch_bounds__(THREADS, 2)
cgemm_nt(const float* __restrict__ bias_re, const float* __restrict__ bias_im,
         const float* __restrict__ mrb,
         int m_base, int N, int K, size_t bias_lim) {
    extern __shared__ uint32_t s[];
    const uint32_t smem_b = (uint32_t)__cvta_generic_to_shared(s);

    const int tid = threadIdx.x;
    const int lane = tid & 31;
    const int warp = tid >> 5;
    const int wm = warp >> 1;
    const int wn = warp & 1;
    const int g  = lane >> 2;
    const int tg = lane & 3;
    const int m0 = blockIdx.y * BM;
    const int n0 = blockIdx.x * BN;

    const uint32_t* Apl[4];
    const uint32_t* Bpl[4];
    int a_row0;
    if (PHASE == 0) {
        Apl[0] = g_cX_hr; Apl[1] = g_cX_lr; Apl[2] = g_cX_hi; Apl[3] = g_cX_li;
        Bpl[0] = g_cWu_hr; Bpl[1] = g_cWu_lr; Bpl[2] = g_cWu_hi; Bpl[3] = g_cWu_li;
        a_row0 = m_base;
    } else {
        Apl[0] = g_cUp_hr; Apl[1] = g_cUp_lr; Apl[2] = g_cUp_hi; Apl[3] = g_cUp_li;
        Bpl[0] = g_cWd_hr; Bpl[1] = g_cWd_lr; Bpl[2] = g_cWd_hi; Bpl[3] = g_cWd_li;
        a_row0 = 0;
    }
    const int rw = K / 2;  // global plane row length in words

    // ---- A-side ldmatrix per-lane swizzled offsets (verified in R11) ----
    const int lrow = lane & 7;
    const int quad = lane >> 3;
    const int rsel = ((quad & 1) << 3) + lrow;
    const int csel = quad >> 1;
    int offA[2][2];
#pragma unroll
    for (int mi = 0; mi < 2; mi++) {
        int r = wm * 32 + mi * 16 + rsel;
#pragma unroll
        for (int ks = 0; ks < 2; ks++)
            offA[mi][ks] = r * RW + (((ks * 2 + csel) ^ ((r >> 1) & 3)) << 2);
    }

    float accRe[2][4][4], accIm[2][4][4];
#pragma unroll
    for (int mi = 0; mi < 2; mi++)
#pragma unroll
        for (int ni = 0; ni < 4; ni++)
#pragma unroll
            for (int r = 0; r < 4; r++) { accRe[mi][ni][r] = 0.f; accIm[mi][ni][r] = 0.f; }

    // Stage loader: 3072 16B chunks / 256 threads = 12 each.
    auto load_stage = [&](int buf, int k0) {
        const int kw0 = k0 >> 1;
        const uint32_t sb = smem_b + (uint32_t)buf * STAGE_W * 4;
#pragma unroll
        for (int t = 0; t < 8; t++) {
            int c = tid + t * THREADS;       // A: 0..2047
            int p = c >> 9;
            int r = (c >> 2) & 127;
            int kc = c & 3;
            const uint32_t* src = Apl[p] + (size_t)(a_row0 + m0 + r) * rw + kw0 + kc * 4;
            int w = r * RW + ((kc ^ ((r >> 1) & 3)) << 2);
            cpasync16(sb + (uint32_t)(p * A_PL + w) * 4, src);
        }
#pragma unroll
        for (int t = 0; t < 4; t++) {
            int c = tid + t * THREADS;       // B: 0..1023
            int p = c >> 8;
            int r = (c >> 2) & 63;
            int kc = c & 3;
            const uint32_t* src = Bpl[p] + (size_t)(n0 + r) * rw + kw0 + kc * 4;
            int w = r * RW + ((kc ^ ((r >> 1) & 3)) << 2);
            cpasync16(sb + (uint32_t)(B_OFF + p * B_PL + w) * 4, src);
        }
        CP_COMMIT();
    };

    const int NK = K / BK;
    load_stage(0, 0);

    for (int it = 0; it < NK; it++) {
        if (it + 1 < NK) {
            load_stage((it + 1) & 1, (it + 1) * BK);
            cp_wait<1>();
        } else {
            cp_wait<0>();
        }
        __syncthreads();

        const int st = (it & 1) * STAGE_W;
        const uint32_t sb = smem_b + (uint32_t)st * 4;
        const int BHR = st + B_OFF, BLR = BHR + B_PL, BHI = BHR + 2 * B_PL, BLI = BHR + 3 * B_PL;

#pragma unroll
        for (int ks = 0; ks < 2; ks++) {
            // ---- B fragments: scalar LDS (R10 path, no permutes) ----
            uint32_t Brh[4][2], Brl[4][2], Bih[4][2], Bil[4][2];
#pragma unroll
            for (int ni = 0; ni < 4; ni++) {
                const int rb = wn * 32 + ni * 8 + g;
                const int w0 = swz(rb, ks * 8 + tg);
                const int w1 = swz(rb, ks * 8 + tg + 4);
                Brh[ni][0] = s[BHR + w0]; Brh[ni][1] = s[BHR + w1];
                Brl[ni][0] = s[BLR + w0]; Brl[ni][1] = s[BLR + w1];
                Bih[ni][0] = s[BHI + w0]; Bih[ni][1] = s[BHI + w1];
                Bil[ni][0] = s[BLI + w0]; Bil[ni][1] = s[BLI + w1];
            }
            // ---- A fragments: ldmatrix x4 (no permutes needed) ----
            uint32_t Arh[2][4], Arl[2][4], Aih[2][4], Ail[2][4], nAih[2][4], nAil[2][4];
#pragma unroll
            for (int mi = 0; mi < 2; mi++) {
                const uint32_t a = sb + (uint32_t)offA[mi][ks] * 4;
                LDSM4(Arh[mi], a);
                LDSM4(Arl[mi], a + A_PL * 4);
                LDSM4(Aih[mi], a + 2 * A_PL * 4);
                LDSM4(Ail[mi], a + 3 * A_PL * 4);
#pragma unroll
                for (int r = 0; r < 4; r++) {
                    nAih[mi][r] = Aih[mi][r] ^ 0x80008000u;
                    nAil[mi][r] = Ail[mi][r] ^ 0x80008000u;
                }
            }
#pragma unroll
            for (int mi = 0; mi < 2; mi++) {
#pragma unroll
                for (int ni = 0; ni < 4; ni++) {
                    mma16816(accRe[mi][ni], Arh[mi],  Brh[ni]);
                    mma16816(accRe[mi][ni], Arh[mi],  Brl[ni]);
                    mma16816(accRe[mi][ni], Arl[mi],  Brh[ni]);
                    mma16816(accRe[mi][ni], nAih[mi], Bih[ni]);
                    mma16816(accRe[mi][ni], nAih[mi], Bil[ni]);
                    mma16816(accRe[mi][ni], nAil[mi], Bih[ni]);
                    mma16816(accIm[mi][ni], Arh[mi],  Bih[ni]);
                    mma16816(accIm[mi][ni], Arh[mi],  Bil[ni]);
                    mma16816(accIm[mi][ni], Arl[mi],  Bih[ni]);
                    mma16816(accIm[mi][ni], Aih[mi],  Brh[ni]);
                    mma16816(accIm[mi][ni], Aih[mi],  Brl[ni]);
                    mma16816(accIm[mi][ni], Ail[mi],  Brh[ni]);
                }
            }
        }
        __syncthreads();
    }

    // ---- epilogue ----
    const bool bias_ok = (PHASE != 0) || ((size_t)n0 + BN <= bias_lim);
#pragma unroll
    for (int mi = 0; mi < 2; mi++) {
#pragma unroll
        for (int ni = 0; ni < 4; ni++) {
            const int col = n0 + wn * 32 + ni * 8 + 2 * tg;   // even
#pragma unroll
            for (int h = 0; h < 2; h++) {
                const int row = m0 + wm * 32 + mi * 16 + g + h * 8;
                float re0 = accRe[mi][ni][2 * h], re1 = accRe[mi][ni][2 * h + 1];
                float im0 = accIm[mi][ni][2 * h], im1 = accIm[mi][ni][2 * h + 1];
                if (PHASE == 0) {
                    float br0 = 0.f, br1 = 0.f, bi0 = 0.f, bi1 = 0.f, mb0 = 0.f, mb1 = 0.f;
                    if (bias_ok) {
                        br0 = bias_re[col]; br1 = bias_re[col + 1];
                        bi0 = bias_im[col]; bi1 = bias_im[col + 1];
                        mb0 = mrb[col];     mb1 = mrb[col + 1];
                    }
                    re0 += br0; im0 += bi0; re1 += br1; im1 += bi1;
                    float mag0 = sqrtf(re0 * re0 + im0 * im0);
                    float mag1 = sqrtf(re1 * re1 + im1 * im1);
                    float s0 = fmaxf(mag0 + mb0, 0.f) / (mag0 + LN_EPS);
                    float s1 = fmaxf(mag1 + mb1, 0.f) / (mag1 + LN_EPS);
                    re0 *= s0; im0 *= s0; re1 *= s1; im1 *= s1;
                    const size_t wo = (size_t)row * (N / 2) + (col >> 1);
                    split2(re0, re1, g_cUp_hr[wo], g_cUp_lr[wo]);
                    split2(im0, im1, g_cUp_hi[wo], g_cUp_li[wo]);
                } else {
                    const size_t off = (size_t)row * N + col;
                    *reinterpret_cast<float2*>(g_dn_re + off) = make_float2(re0, re1);
                    *reinterpret_cast<float2*>(g_dn_im + off) = make_float2(im0, im1);
                }
            }
        }
    }
}

// Complex LayerNorm over D + residual, one block per (chunk-local) token row.
template <int OUT_MODE>
__global__ void __launch_bounds__(256)
ln_res_kernel(const float* __restrict__ xr, const float* __restrict__ xi,
              const float* __restrict__ gr, const float* __restrict__ gi,
              const float* __restrict__ br, const float* __restrict__ bi,
              float* __restrict__ out, int m_base,
              size_t x_lim, size_t p_lim, size_t out_cap) {
    const int m = blockIdx.x;
    const size_t base = (size_t)m * CD;
    const size_t gbase = (size_t)(m_base + m) * CD;
    const int tid = threadIdx.x;
    const bool x_ok = (gbase + CD) <= x_lim;
    const bool p_ok = (size_t)CD <= p_lim;

    float sr = 0.f, si = 0.f, sq = 0.f;
    for (int d = tid; d < CD; d += 256) {
        float r = g_dn_re[base + d];
        float q = g_dn_im[base + d];
        sr += r; si += q; sq += r * r + q * q;
    }
    __shared__ float red0[256], red1[256], red2[256];
    red0[tid] = sr; red1[tid] = si; red2[tid] = sq;
    __syncthreads();
    for (int st = 128; st > 0; st >>= 1) {
        if (tid < st) {
            red0[tid] += red0[tid + st];
            red1[tid] += red1[tid + st];
            red2[tid] += red2[tid + st];
        }
        __syncthreads();
    }
    const float inv_d = 1.f / (float)CD;
    const float mur = red0[0] * inv_d;
    const float mui = red1[0] * inv_d;
    const float var = red2[0] * inv_d - (mur * mur + mui * mui);
    const float rstd = rsqrtf(var + LN_EPS);

    for (int d = tid; d < CD; d += 256) {
        float zr = (g_dn_re[base + d] - mur) * rstd;
        float zi = (g_dn_im[base + d] - mui) * rstd;
        float g_r = p_ok ? gr[d] : 1.f;
        float g_i = p_ok ? gi[d] : 0.f;
        float b_r = p_ok ? br[d] : 0.f;
        float b_i = p_ok ? bi[d] : 0.f;
        float xre = x_ok ? xr[gbase + d] : 0.f;
        float xim = x_ok ? xi[gbase + d] : 0.f;
        float o_r = g_r * zr - g_i * zi + b_r + xre;
        float o_i = g_r * zi + g_i * zr + b_i + xim;
        if (OUT_MODE == 0) {
            const size_t fo = gbase + d;
            if (fo < out_cap) out[fo] = o_r;
        } else {
            const size_t fo = 2 * (gbase + d);
            if (fo + 1 < out_cap) { out[fo] = o_r; out[fo + 1] = o_i; }
        }
    }
}

// ---------------- host-side binding ----------------
static bool match_sig(const int* s, const long long* want, long long scale) {
    for (int i = 0; i < 13; i++)
        if ((long long)s[i] != want[i] * scale) return false;
    return true;
}

extern "C" void kernel_launch(void* const* d_in, const int* in_sizes, int n_in,
                              void* d_out, int out_size) {
    if (n_in < 13) return;
    for (int i = 0; i < 13; i++) if (d_in[i] == nullptr) return;

    static const long long SIG_DICT[13] =
        {16777216,16777216,16777216,16777216,8192,8192,8192,
         16777216,16777216,2048,2048,2048,2048};
    static const long long SIG_ALPHA[13] =
        {16777216,16777216,16777216,16777216,8192,8192,
         2048,2048,2048,2048,8192,16777216,16777216};

    int order = 0;
    long long unit = 1;
    if (match_sig(in_sizes, SIG_DICT, 1))       { order = 0; unit = 1; }
    else if (match_sig(in_sizes, SIG_ALPHA, 1)) { order = 1; unit = 1; }
    else if (match_sig(in_sizes, SIG_DICT, 4))  { order = 0; unit = 4; }
    else if (match_sig(in_sizes, SIG_ALPHA, 4)) { order = 1; unit = 4; }

    const float *x_re, *x_im, *Wup_re, *Wup_im, *bias_re, *bias_im, *mrb;
    const float *Wd_re, *Wd_im, *g_re, *g_im, *be_re, *be_im;
    size_t sz[13];
    for (int i = 0; i < 13; i++) sz[i] = (size_t)((long long)in_sizes[i] / unit);
    size_t x_lim, wup_lim, wd_lim, bias_lim, ln_lim;

    if (order == 0) {
        x_re   = (const float*)d_in[0];  x_im   = (const float*)d_in[1];
        Wup_re = (const float*)d_in[2];  Wup_im = (const float*)d_in[3];
        bias_re = (const float*)d_in[4]; bias_im = (const float*)d_in[5];
        mrb    = (const float*)d_in[6];
        Wd_re  = (const float*)d_in[7];  Wd_im  = (const float*)d_in[8];
        g_re   = (const float*)d_in[9];  g_im   = (const float*)d_in[10];
        be_re  = (const float*)d_in[11]; be_im  = (const float*)d_in[12];
        x_lim = sz[0] < sz[1] ? sz[0] : sz[1];
        wup_lim = sz[2] < sz[3] ? sz[2] : sz[3];
        bias_lim = sz[4] < sz[5] ? sz[4] : sz[5];
        if (sz[6] < bias_lim) bias_lim = sz[6];
        wd_lim = sz[7] < sz[8] ? sz[7] : sz[8];
        ln_lim = sz[9];
        for (int i = 10; i <= 12; i++) if (sz[i] < ln_lim) ln_lim = sz[i];
    } else {
        Wd_im  = (const float*)d_in[0];  Wd_re  = (const float*)d_in[1];
        Wup_im = (const float*)d_in[2];  Wup_re = (const float*)d_in[3];
        bias_im = (const float*)d_in[4]; bias_re = (const float*)d_in[5];
        be_im  = (const float*)d_in[6];  be_re  = (const float*)d_in[7];
        g_im   = (const float*)d_in[8];  g_re   = (const float*)d_in[9];
        mrb    = (const float*)d_in[10];
        x_im   = (const float*)d_in[11]; x_re   = (const float*)d_in[12];
        wd_lim = sz[0] < sz[1] ? sz[0] : sz[1];
        wup_lim = sz[2] < sz[3] ? sz[2] : sz[3];
        bias_lim = sz[4] < sz[5] ? sz[4] : sz[5];
        if (sz[10] < bias_lim) bias_lim = sz[10];
        ln_lim = sz[6];
        for (int i = 7; i <= 9; i++) if (sz[i] < ln_lim) ln_lim = sz[i];
        x_lim = sz[11] < sz[12] ? sz[11] : sz[12];
    }

    const bool real_only = ((long long)out_size == 16777216LL);
    const size_t out_cap = (size_t)(long long)out_size;

    static bool attr_done = false;
    if (!attr_done) {
        cudaFuncSetAttribute(cgemm_nt<0>, cudaFuncAttributeMaxDynamicSharedMemorySize, SMEM_BYTES);
        cudaFuncSetAttribute(cgemm_nt<1>, cudaFuncAttributeMaxDynamicSharedMemorySize, SMEM_BYTES);
        attr_done = true;
    }

    // ---- pre-convert x, Wup, Wdown to packed bf16 hi/lo planes ----
    uint32_t *cx0, *cx1, *cx2, *cx3, *cu0, *cu1, *cu2, *cu3, *cd0, *cd1, *cd2, *cd3;
    cudaGetSymbolAddress((void**)&cx0, g_cX_hr);  cudaGetSymbolAddress((void**)&cx1, g_cX_lr);
    cudaGetSymbolAddress((void**)&cx2, g_cX_hi);  cudaGetSymbolAddress((void**)&cx3, g_cX_li);
    cudaGetSymbolAddress((void**)&cu0, g_cWu_hr); cudaGetSymbolAddress((void**)&cu1, g_cWu_lr);
    cudaGetSymbolAddress((void**)&cu2, g_cWu_hi); cudaGetSymbolAddress((void**)&cu3, g_cWu_li);
    cudaGetSymbolAddress((void**)&cd0, g_cWd_hr); cudaGetSymbolAddress((void**)&cd1, g_cWd_lr);
    cudaGetSymbolAddress((void**)&cd2, g_cWd_hi); cudaGetSymbolAddress((void**)&cd3, g_cWd_li);

    {
        int gx = (int)((XW + 255) / 256);
        conv_kernel<<<gx, 256>>>(x_re, x_im, cx0, cx1, cx2, cx3, XW, x_lim);
        int gw = (int)((WW + 255) / 256);
        conv_kernel<<<gw, 256>>>(Wup_re, Wup_im, cu0, cu1, cu2, cu3, WW, wup_lim);
        conv_kernel<<<gw, 256>>>(Wd_re, Wd_im, cd0, cd1, cd2, cd3, WW, wd_lim);
    }

    for (int c = 0; c < NCHUNKS; c++) {
        const int mb = c * MCHUNK;
        dim3 g1(CF / BN, MCHUNK / BM);
        cgemm_nt<0><<<g1, THREADS, SMEM_BYTES>>>(bias_re, bias_im, mrb,
                                                 mb, CF, CD, bias_lim);
        dim3 g2(CD / BN, MCHUNK / BM);
        cgemm_nt<1><<<g2, THREADS, SMEM_BYTES>>>(nullptr, nullptr, nullptr,
                                                 mb, CD, CF, 0);
        if (real_only) {
            ln_res_kernel<0><<<MCHUNK, 256>>>(x_re, x_im, g_re, g_im,
                                              be_re, be_im, (float*)d_out, mb,
                                              x_lim, ln_lim, out_cap);
        } else {
            ln_res_kernel<1><<<MCHUNK, 256>>>(x_re, x_im, g_re, g_im,
                                              be_re, be_im, (float*)d_out, mb,
                                              x_lim, ln_lim, out_cap);
        }
    }
}

// round 15
// speedup vs baseline: 1.2795x; 1.0519x over previous
#include <cuda_runtime.h>
#include <cuda_bf16.h>
#include <math.h>
#include <stdint.h>

#define LN_EPS 1e-5f

// Problem constants
constexpr int CB = 4, CS = 2048, CD = 2048, CF = 8192;
constexpr int CM = CB * CS;
constexpr int MCHUNK = 2048;
constexpr int NCHUNKS = CM / MCHUNK;

// GEMM tiling
constexpr int BM = 128, BN = 64, BK = 32;
constexpr int THREADS = 256;     // 8 warps: 4 (M) x 2 (N)
constexpr int RW = 16;           // smem row pitch in words (swizzled, no pad)

// Smem layout (words): per stage, 4 A planes then 4 B planes.
constexpr int A_PL = BM * RW;                // 2048 words
constexpr int B_PL = BN * RW;                // 1024 words
constexpr int B_OFF = 4 * A_PL;              // 8192
constexpr int STAGE_W = 4 * A_PL + 4 * B_PL; // 12288 words
constexpr int SMEM_BYTES = 2 * STAGE_W * 4;  // 98304 B -> 2 CTAs/SM

// ---- device-global scratch: packed bf16x2 hi/lo planes (word = k,k+1) ----
constexpr size_t XW = (size_t)CM * CD / 2;
constexpr size_t WW = (size_t)CF * CD / 2;
constexpr size_t UW = (size_t)MCHUNK * CF / 2;
__device__ __align__(16) uint32_t g_cX_hr[XW], g_cX_lr[XW], g_cX_hi[XW], g_cX_li[XW];
__device__ __align__(16) uint32_t g_cWu_hr[WW], g_cWu_lr[WW], g_cWu_hi[WW], g_cWu_li[WW];
__device__ __align__(16) uint32_t g_cWd_hr[WW], g_cWd_lr[WW], g_cWd_hi[WW], g_cWd_li[WW];
__device__ __align__(16) uint32_t g_cUp_hr[UW], g_cUp_lr[UW], g_cUp_hi[UW], g_cUp_li[UW];
__device__ __align__(16) float g_dn_re[(size_t)MCHUNK * CD];
__device__ __align__(16) float g_dn_im[(size_t)MCHUNK * CD];

// Split two fp32 into packed bf16 hi / lo words
__device__ __forceinline__ void split2(float x, float y, uint32_t& hi, uint32_t& lo) {
    __nv_bfloat16 xh = __float2bfloat16_rn(x);
    __nv_bfloat16 yh = __float2bfloat16_rn(y);
    float xr = x - __bfloat162float(xh);
    float yr = y - __bfloat162float(yh);
    __nv_bfloat16 xl = __float2bfloat16_rn(xr);
    __nv_bfloat16 yl = __float2bfloat16_rn(yr);
    hi = (uint32_t)__bfloat16_as_ushort(xh) | ((uint32_t)__bfloat16_as_ushort(yh) << 16);
    lo = (uint32_t)__bfloat16_as_ushort(xl) | ((uint32_t)__bfloat16_as_ushort(yl) << 16);
}

__device__ __forceinline__ void mma16816(float* c, const uint32_t* a, const uint32_t* b) {
    asm volatile(
        "mma.sync.aligned.m16n8k16.row.col.f32.bf16.bf16.f32 "
        "{%0,%1,%2,%3}, {%4,%5,%6,%7}, {%8,%9}, {%0,%1,%2,%3};\n"
        : "+f"(c[0]), "+f"(c[1]), "+f"(c[2]), "+f"(c[3])
        : "r"(a[0]), "r"(a[1]), "r"(a[2]), "r"(a[3]), "r"(b[0]), "r"(b[1]));
}

#define LDSM4(r, addr) \
    asm volatile("ldmatrix.sync.aligned.m8n8.x4.shared.b16 {%0,%1,%2,%3}, [%4];" \
        : "=r"((r)[0]), "=r"((r)[1]), "=r"((r)[2]), "=r"((r)[3]) : "r"(addr))

__device__ __forceinline__ void cpasync16(uint32_t smem_bytes_addr, const void* g) {
    asm volatile("cp.async.cg.shared.global [%0], [%1], 16;\n"
                 :: "r"(smem_bytes_addr), "l"(g));
}
#define CP_COMMIT() asm volatile("cp.async.commit_group;\n")
template <int N>
__device__ __forceinline__ void cp_wait() {
    asm volatile("cp.async.wait_group %0;\n" :: "n"(N));
}

// Pre-conversion: fp32 planar -> packed bf16x2 hi/lo planes.
__global__ void __launch_bounds__(256)
conv_kernel(const float* __restrict__ re, const float* __restrict__ im,
            uint32_t* __restrict__ hr, uint32_t* __restrict__ lr,
            uint32_t* __restrict__ hi_, uint32_t* __restrict__ li,
            size_t nwords, size_t lim) {
    size_t i = (size_t)blockIdx.x * 256 + threadIdx.x;
    if (i >= nwords) return;
    size_t e = 2 * i;
    float r0 = 0.f, r1 = 0.f, q0 = 0.f, q1 = 0.f;
    if (e + 2 <= lim) {
        float2 v = *reinterpret_cast<const float2*>(re + e);
        float2 w = *reinterpret_cast<const float2*>(im + e);
        r0 = v.x; r1 = v.y; q0 = w.x; q1 = w.y;
    }
    split2(r0, r1, hr[i], lr[i]);
    split2(q0, q1, hi_[i], li[i]);
}

// Complex NT GEMM: R14 + B-side ldmatrix with permute-free quad mapping.
// PHASE 0: A = g_cX (rows m_base+..), B = g_cWu, epi = bias+modrelu -> g_cUp
// PHASE 1: A = g_cUp (chunk-local), B = g_cWd, epi = plain -> g_dn
template <int PHASE>
__global__ void __launch_bounds__(THREADS, 2)
cgemm_nt(const float* __restrict__ bias_re, const float* __restrict__ bias_im,
         const float* __restrict__ mrb,
         int m_base, int N, int K, size_t bias_lim) {
    extern __shared__ uint32_t s[];
    const uint32_t smem_b = (uint32_t)__cvta_generic_to_shared(s);

    const int tid = threadIdx.x;
    const int lane = tid & 31;
    const int warp = tid >> 5;
    const int wm = warp >> 1;
    const int wn = warp & 1;
    const int g  = lane >> 2;
    const int tg = lane & 3;
    const int m0 = blockIdx.y * BM;
    const int n0 = blockIdx.x * BN;

    const uint32_t* Apl[4];
    const uint32_t* Bpl[4];
    int a_row0;
    if (PHASE == 0) {
        Apl[0] = g_cX_hr; Apl[1] = g_cX_lr; Apl[2] = g_cX_hi; Apl[3] = g_cX_li;
        Bpl[0] = g_cWu_hr; Bpl[1] = g_cWu_lr; Bpl[2] = g_cWu_hi; Bpl[3] = g_cWu_li;
        a_row0 = m_base;
    } else {
        Apl[0] = g_cUp_hr; Apl[1] = g_cUp_lr; Apl[2] = g_cUp_hi; Apl[3] = g_cUp_li;
        Bpl[0] = g_cWd_hr; Bpl[1] = g_cWd_lr; Bpl[2] = g_cWd_hi; Bpl[3] = g_cWd_li;
        a_row0 = 0;
    }
    const int rw = K / 2;  // global plane row length in words

    const int lrow = lane & 7;
    const int quad = lane >> 3;

    // ---- A-side ldmatrix offsets (R14 mapping: quad = (chunk<<1)|rowhalf) ----
    // quad0: rows +0..7 chunk+0, quad1: rows +8..15 chunk+0,
    // quad2: rows +0..7 chunk+1, quad3: rows +8..15 chunk+1
    // -> regs a0..a3 in mma order.
    int offA[2][2];
    {
        const int rselA = ((quad & 1) << 3) + lrow;
        const int cselA = quad >> 1;
#pragma unroll
        for (int mi = 0; mi < 2; mi++) {
            int r = wm * 32 + mi * 16 + rselA;
#pragma unroll
            for (int ks = 0; ks < 2; ks++)
                offA[mi][ks] = r * RW + (((ks * 2 + cselA) ^ ((r >> 1) & 3)) << 2);
        }
    }
    // ---- B-side ldmatrix offsets (permute-free: quad = (rowblock<<1)|chunk) ----
    // quad0: rows ni*8 chunk+0      -> reg0 = b0(ni)
    // quad1: rows ni*8 chunk+1      -> reg1 = b1(ni)
    // quad2: rows (ni+1)*8 chunk+0  -> reg2 = b0(ni+1)
    // quad3: rows (ni+1)*8 chunk+1  -> reg3 = b1(ni+1)
    int offB[2][2];
    {
        const int rselB = ((quad >> 1) << 3) + lrow;
        const int cselB = quad & 1;
#pragma unroll
        for (int p = 0; p < 2; p++) {
            int r = wn * 32 + p * 16 + rselB;
#pragma unroll
            for (int ks = 0; ks < 2; ks++)
                offB[p][ks] = r * RW + (((ks * 2 + cselB) ^ ((r >> 1) & 3)) << 2);
        }
    }

    float accRe[2][4][4], accIm[2][4][4];
#pragma unroll
    for (int mi = 0; mi < 2; mi++)
#pragma unroll
        for (int ni = 0; ni < 4; ni++)
#pragma unroll
            for (int r = 0; r < 4; r++) { accRe[mi][ni][r] = 0.f; accIm[mi][ni][r] = 0.f; }

    // Stage loader: 3072 16B chunks / 256 threads = 12 each.
    auto load_stage = [&](int buf, int k0) {
        const int kw0 = k0 >> 1;
        const uint32_t sb = smem_b + (uint32_t)buf * STAGE_W * 4;
#pragma unroll
        for (int t = 0; t < 8; t++) {
            int c = tid + t * THREADS;       // A: 0..2047
            int p = c >> 9;
            int r = (c >> 2) & 127;
            int kc = c & 3;
            const uint32_t* src = Apl[p] + (size_t)(a_row0 + m0 + r) * rw + kw0 + kc * 4;
            int w = r * RW + ((kc ^ ((r >> 1) & 3)) << 2);
            cpasync16(sb + (uint32_t)(p * A_PL + w) * 4, src);
        }
#pragma unroll
        for (int t = 0; t < 4; t++) {
            int c = tid + t * THREADS;       // B: 0..1023
            int p = c >> 8;
            int r = (c >> 2) & 63;
            int kc = c & 3;
            const uint32_t* src = Bpl[p] + (size_t)(n0 + r) * rw + kw0 + kc * 4;
            int w = r * RW + ((kc ^ ((r >> 1) & 3)) << 2);
            cpasync16(sb + (uint32_t)(B_OFF + p * B_PL + w) * 4, src);
        }
        CP_COMMIT();
    };

    const int NK = K / BK;
    load_stage(0, 0);

    for (int it = 0; it < NK; it++) {
        if (it + 1 < NK) {
            load_stage((it + 1) & 1, (it + 1) * BK);
            cp_wait<1>();
        } else {
            cp_wait<0>();
        }
        __syncthreads();

        const uint32_t sb = smem_b + (uint32_t)((it & 1) * STAGE_W) * 4;

#pragma unroll
        for (int ks = 0; ks < 2; ks++) {
            // ---- B fragments: ldmatrix x4 (regs land directly in [ni][2] order) ----
            uint32_t Brh[4][2], Brl[4][2], Bih[4][2], Bil[4][2];
#pragma unroll
            for (int p = 0; p < 2; p++) {
                const uint32_t b = sb + (uint32_t)(B_OFF + offB[p][ks]) * 4;
                LDSM4(&Brh[2 * p][0], b);
                LDSM4(&Brl[2 * p][0], b + B_PL * 4);
                LDSM4(&Bih[2 * p][0], b + 2 * B_PL * 4);
                LDSM4(&Bil[2 * p][0], b + 3 * B_PL * 4);
            }
            // ---- A fragments: ldmatrix x4 (R14 path) ----
            uint32_t Arh[2][4], Arl[2][4], Aih[2][4], Ail[2][4], nAih[2][4], nAil[2][4];
#pragma unroll
            for (int mi = 0; mi < 2; mi++) {
                const uint32_t a = sb + (uint32_t)offA[mi][ks] * 4;
                LDSM4(Arh[mi], a);
                LDSM4(Arl[mi], a + A_PL * 4);
                LDSM4(Aih[mi], a + 2 * A_PL * 4);
                LDSM4(Ail[mi], a + 3 * A_PL * 4);
#pragma unroll
                for (int r = 0; r < 4; r++) {
                    nAih[mi][r] = Aih[mi][r] ^ 0x80008000u;
                    nAil[mi][r] = Ail[mi][r] ^ 0x80008000u;
                }
            }
#pragma unroll
            for (int mi = 0; mi < 2; mi++) {
#pragma unroll
                for (int ni = 0; ni < 4; ni++) {
                    mma16816(accRe[mi][ni], Arh[mi],  Brh[ni]);
                    mma16816(accRe[mi][ni], Arh[mi],  Brl[ni]);
                    mma16816(accRe[mi][ni], Arl[mi],  Brh[ni]);
                    mma16816(accRe[mi][ni], nAih[mi], Bih[ni]);
                    mma16816(accRe[mi][ni], nAih[mi], Bil[ni]);
                    mma16816(accRe[mi][ni], nAil[mi], Bih[ni]);
                    mma16816(accIm[mi][ni], Arh[mi],  Bih[ni]);
                    mma16816(accIm[mi][ni], Arh[mi],  Bil[ni]);
                    mma16816(accIm[mi][ni], Arl[mi],  Bih[ni]);
                    mma16816(accIm[mi][ni], Aih[mi],  Brh[ni]);
                    mma16816(accIm[mi][ni], Aih[mi],  Brl[ni]);
                    mma16816(accIm[mi][ni], Ail[mi],  Brh[ni]);
                }
            }
        }
        __syncthreads();
    }

    // ---- epilogue ----
    const bool bias_ok = (PHASE != 0) || ((size_t)n0 + BN <= bias_lim);
#pragma unroll
    for (int mi = 0; mi < 2; mi++) {
#pragma unroll
        for (int ni = 0; ni < 4; ni++) {
            const int col = n0 + wn * 32 + ni * 8 + 2 * tg;   // even
#pragma unroll
            for (int h = 0; h < 2; h++) {
                const int row = m0 + wm * 32 + mi * 16 + g + h * 8;
                float re0 = accRe[mi][ni][2 * h], re1 = accRe[mi][ni][2 * h + 1];
                float im0 = accIm[mi][ni][2 * h], im1 = accIm[mi][ni][2 * h + 1];
                if (PHASE == 0) {
                    float br0 = 0.f, br1 = 0.f, bi0 = 0.f, bi1 = 0.f, mb0 = 0.f, mb1 = 0.f;
                    if (bias_ok) {
                        br0 = bias_re[col]; br1 = bias_re[col + 1];
                        bi0 = bias_im[col]; bi1 = bias_im[col + 1];
                        mb0 = mrb[col];     mb1 = mrb[col + 1];
                    }
                    re0 += br0; im0 += bi0; re1 += br1; im1 += bi1;
                    float mag0 = sqrtf(re0 * re0 + im0 * im0);
                    float mag1 = sqrtf(re1 * re1 + im1 * im1);
                    float s0 = fmaxf(mag0 + mb0, 0.f) / (mag0 + LN_EPS);
                    float s1 = fmaxf(mag1 + mb1, 0.f) / (mag1 + LN_EPS);
                    re0 *= s0; im0 *= s0; re1 *= s1; im1 *= s1;
                    const size_t wo = (size_t)row * (N / 2) + (col >> 1);
                    split2(re0, re1, g_cUp_hr[wo], g_cUp_lr[wo]);
                    split2(im0, im1, g_cUp_hi[wo], g_cUp_li[wo]);
                } else {
                    const size_t off = (size_t)row * N + col;
                    *reinterpret_cast<float2*>(g_dn_re + off) = make_float2(re0, re1);
                    *reinterpret_cast<float2*>(g_dn_im + off) = make_float2(im0, im1);
                }
            }
        }
    }
}

// Complex LayerNorm over D + residual, one block per (chunk-local) token row.
template <int OUT_MODE>
__global__ void __launch_bounds__(256)
ln_res_kernel(const float* __restrict__ xr, const float* __restrict__ xi,
              const float* __restrict__ gr, const float* __restrict__ gi,
              const float* __restrict__ br, const float* __restrict__ bi,
              float* __restrict__ out, int m_base,
              size_t x_lim, size_t p_lim, size_t out_cap) {
    const int m = blockIdx.x;
    const size_t base = (size_t)m * CD;
    const size_t gbase = (size_t)(m_base + m) * CD;
    const int tid = threadIdx.x;
    const bool x_ok = (gbase + CD) <= x_lim;
    const bool p_ok = (size_t)CD <= p_lim;

    float sr = 0.f, si = 0.f, sq = 0.f;
    for (int d = tid; d < CD; d += 256) {
        float r = g_dn_re[base + d];
        float q = g_dn_im[base + d];
        sr += r; si += q; sq += r * r + q * q;
    }
    __shared__ float red0[256], red1[256], red2[256];
    red0[tid] = sr; red1[tid] = si; red2[tid] = sq;
    __syncthreads();
    for (int st = 128; st > 0; st >>= 1) {
        if (tid < st) {
            red0[tid] += red0[tid + st];
            red1[tid] += red1[tid + st];
            red2[tid] += red2[tid + st];
        }
        __syncthreads();
    }
    const float inv_d = 1.f / (float)CD;
    const float mur = red0[0] * inv_d;
    const float mui = red1[0] * inv_d;
    const float var = red2[0] * inv_d - (mur * mur + mui * mui);
    const float rstd = rsqrtf(var + LN_EPS);

    for (int d = tid; d < CD; d += 256) {
        float zr = (g_dn_re[base + d] - mur) * rstd;
        float zi = (g_dn_im[base + d] - mui) * rstd;
        float g_r = p_ok ? gr[d] : 1.f;
        float g_i = p_ok ? gi[d] : 0.f;
        float b_r = p_ok ? br[d] : 0.f;
        float b_i = p_ok ? bi[d] : 0.f;
        float xre = x_ok ? xr[gbase + d] : 0.f;
        float xim = x_ok ? xi[gbase + d] : 0.f;
        float o_r = g_r * zr - g_i * zi + b_r + xre;
        float o_i = g_r * zi + g_i * zr + b_i + xim;
        if (OUT_MODE == 0) {
            const size_t fo = gbase + d;
            if (fo < out_cap) out[fo] = o_r;
        } else {
            const size_t fo = 2 * (gbase + d);
            if (fo + 1 < out_cap) { out[fo] = o_r; out[fo + 1] = o_i; }
        }
    }
}

// ---------------- host-side binding ----------------
static bool match_sig(const int* s, const long long* want, long long scale) {
    for (int i = 0; i < 13; i++)
        if ((long long)s[i] != want[i] * scale) return false;
    return true;
}

extern "C" void kernel_launch(void* const* d_in, const int* in_sizes, int n_in,
                              void* d_out, int out_size) {
    if (n_in < 13) return;
    for (int i = 0; i < 13; i++) if (d_in[i] == nullptr) return;

    static const long long SIG_DICT[13] =
        {16777216,16777216,16777216,16777216,8192,8192,8192,
         16777216,16777216,2048,2048,2048,2048};
    static const long long SIG_ALPHA[13] =
        {16777216,16777216,16777216,16777216,8192,8192,
         2048,2048,2048,2048,8192,16777216,16777216};

    int order = 0;
    long long unit = 1;
    if (match_sig(in_sizes, SIG_DICT, 1))       { order = 0; unit = 1; }
    else if (match_sig(in_sizes, SIG_ALPHA, 1)) { order = 1; unit = 1; }
    else if (match_sig(in_sizes, SIG_DICT, 4))  { order = 0; unit = 4; }
    else if (match_sig(in_sizes, SIG_ALPHA, 4)) { order = 1; unit = 4; }

    const float *x_re, *x_im, *Wup_re, *Wup_im, *bias_re, *bias_im, *mrb;
    const float *Wd_re, *Wd_im, *g_re, *g_im, *be_re, *be_im;
    size_t sz[13];
    for (int i = 0; i < 13; i++) sz[i] = (size_t)((long long)in_sizes[i] / unit);
    size_t x_lim, wup_lim, wd_lim, bias_lim, ln_lim;

    if (order == 0) {
        x_re   = (const float*)d_in[0];  x_im   = (const float*)d_in[1];
        Wup_re = (const float*)d_in[2];  Wup_im = (const float*)d_in[3];
        bias_re = (const float*)d_in[4]; bias_im = (const float*)d_in[5];
        mrb    = (const float*)d_in[6];
        Wd_re  = (const float*)d_in[7];  Wd_im  = (const float*)d_in[8];
        g_re   = (const float*)d_in[9];  g_im   = (const float*)d_in[10];
        be_re  = (const float*)d_in[11]; be_im  = (const float*)d_in[12];
        x_lim = sz[0] < sz[1] ? sz[0] : sz[1];
        wup_lim = sz[2] < sz[3] ? sz[2] : sz[3];
        bias_lim = sz[4] < sz[5] ? sz[4] : sz[5];
        if (sz[6] < bias_lim) bias_lim = sz[6];
        wd_lim = sz[7] < sz[8] ? sz[7] : sz[8];
        ln_lim = sz[9];
        for (int i = 10; i <= 12; i++) if (sz[i] < ln_lim) ln_lim = sz[i];
    } else {
        Wd_im  = (const float*)d_in[0];  Wd_re  = (const float*)d_in[1];
        Wup_im = (const float*)d_in[2];  Wup_re = (const float*)d_in[3];
        bias_im = (const float*)d_in[4]; bias_re = (const float*)d_in[5];
        be_im  = (const float*)d_in[6];  be_re  = (const float*)d_in[7];
        g_im   = (const float*)d_in[8];  g_re   = (const float*)d_in[9];
        mrb    = (const float*)d_in[10];
        x_im   = (const float*)d_in[11]; x_re   = (const float*)d_in[12];
        wd_lim = sz[0] < sz[1] ? sz[0] : sz[1];
        wup_lim = sz[2] < sz[3] ? sz[2] : sz[3];
        bias_lim = sz[4] < sz[5] ? sz[4] : sz[5];
        if (sz[10] < bias_lim) bias_lim = sz[10];
        ln_lim = sz[6];
        for (int i = 7; i <= 9; i++) if (sz[i] < ln_lim) ln_lim = sz[i];
        x_lim = sz[11] < sz[12] ? sz[11] : sz[12];
    }

    const bool real_only = ((long long)out_size == 16777216LL);
    const size_t out_cap = (size_t)(long long)out_size;

    static bool attr_done = false;
    if (!attr_done) {
        cudaFuncSetAttribute(cgemm_nt<0>, cudaFuncAttributeMaxDynamicSharedMemorySize, SMEM_BYTES);
        cudaFuncSetAttribute(cgemm_nt<1>, cudaFuncAttributeMaxDynamicSharedMemorySize, SMEM_BYTES);
        attr_done = true;
    }

    // ---- pre-convert x, Wup, Wdown to packed bf16 hi/lo planes ----
    uint32_t *cx0, *cx1, *cx2, *cx3, *cu0, *cu1, *cu2, *cu3, *cd0, *cd1, *cd2, *cd3;
    cudaGetSymbolAddress((void**)&cx0, g_cX_hr);  cudaGetSymbolAddress((void**)&cx1, g_cX_lr);
    cudaGetSymbolAddress((void**)&cx2, g_cX_hi);  cudaGetSymbolAddress((void**)&cx3, g_cX_li);
    cudaGetSymbolAddress((void**)&cu0, g_cWu_hr); cudaGetSymbolAddress((void**)&cu1, g_cWu_lr);
    cudaGetSymbolAddress((void**)&cu2, g_cWu_hi); cudaGetSymbolAddress((void**)&cu3, g_cWu_li);
    cudaGetSymbolAddress((void**)&cd0, g_cWd_hr); cudaGetSymbolAddress((void**)&cd1, g_cWd_lr);
    cudaGetSymbolAddress((void**)&cd2, g_cWd_hi); cudaGetSymbolAddress((void**)&cd3, g_cWd_li);

    {
        int gx = (int)((XW + 255) / 256);
        conv_kernel<<<gx, 256>>>(x_re, x_im, cx0, cx1, cx2, cx3, XW, x_lim);
        int gw = (int)((WW + 255) / 256);
        conv_kernel<<<gw, 256>>>(Wup_re, Wup_im, cu0, cu1, cu2, cu3, WW, wup_lim);
        conv_kernel<<<gw, 256>>>(Wd_re, Wd_im, cd0, cd1, cd2, cd3, WW, wd_lim);
    }

    for (int c = 0; c < NCHUNKS; c++) {
        const int mb = c * MCHUNK;
        dim3 g1(CF / BN, MCHUNK / BM);
        cgemm_nt<0><<<g1, THREADS, SMEM_BYTES>>>(bias_re, bias_im, mrb,
                                                 mb, CF, CD, bias_lim);
        dim3 g2(CD / BN, MCHUNK / BM);
        cgemm_nt<1><<<g2, THREADS, SMEM_BYTES>>>(nullptr, nullptr, nullptr,
                                                 mb, CD, CF, 0);
        if (real_only) {
            ln_res_kernel<0><<<MCHUNK, 256>>>(x_re, x_im, g_re, g_im,
                                              be_re, be_im, (float*)d_out, mb,
                                              x_lim, ln_lim, out_cap);
        } else {
            ln_res_kernel<1><<<MCHUNK, 256>>>(x_re, x_im, g_re, g_im,
                                              be_re, be_im, (float*)d_out, mb,
                                              x_lim, ln_lim, out_cap);
        }
    }
}